// round 10
// baseline (speedup 1.0000x reference)
#include <cuda_runtime.h>
#include <cuda_fp16.h>
#include <mma.h>
#include <cstdint>
#include <cstddef>

using namespace nvcuda;

#define B_ROWS 4096
#define D_IN   1024
#define D_H    4096
#define D_OUT  1024
#define NE     8
#define EH     32768
#define NACT   5

// GEMM tiling: CTA 256x128, 16 warps (4x4), warp 64x32, BK=32, 2 stages
#define TM  256
#define BK  32
#define LDA 40     // A smem row stride in halves (80B)
#define LDB 136    // B smem row stride in halves (272B)
#define ASTG_H (TM * LDA)             // 10240 halves
#define BSTG_H (BK * LDB)             // 4352 halves
#define STG_H  (ASTG_H + BSTG_H)      // 14592 halves = 29184 B
#define SMEM_BYTES (2 * STG_H * 2)    // 58368 B

// Scratch (device globals; no allocation allowed)
__device__ float  g_w[B_ROWS * NE];
__device__ int    g_cnt[NE];
__device__ int    g_rows[NE][B_ROWS];
__device__ int    g_slot[B_ROWS * NE];
__device__ __half g_xh[(size_t)B_ROWS * D_IN];
__device__ __half g_w1h[(size_t)NE * D_IN * D_H];
__device__ __half g_w2h[(size_t)EH * D_OUT];
__device__ __half g_hsh[(size_t)B_ROWS * EH];
__device__ float  g_eo[(size_t)NE * B_ROWS * D_OUT];   // slot-indexed

// ---------------------------------------------------------------------------
__device__ __forceinline__ void cp16h(__half* sdst, const __half* gsrc) {
    uint32_t s = (uint32_t)__cvta_generic_to_shared(sdst);
    asm volatile("cp.async.cg.shared.global [%0], [%1], 16;\n" :: "r"(s), "l"(gsrc));
}
#define CP_COMMIT()   asm volatile("cp.async.commit_group;\n")
#define CP_WAIT_ALL() asm volatile("cp.async.wait_group 0;\n" ::: "memory")

// ---------------------------------------------------------------------------
__global__ void zero_cnt_kernel() {
    if (threadIdx.x < NE) g_cnt[threadIdx.x] = 0;
}

__global__ void f2h_kernel(const float4* __restrict__ src, int which, int n4) {
    int i = blockIdx.x * blockDim.x + threadIdx.x;
    if (i >= n4) return;
    float4 v = src[i];
    union { __half2 h2[2]; uint2 u; } cvt;
    cvt.h2[0] = __floats2half2_rn(v.x, v.y);
    cvt.h2[1] = __floats2half2_rn(v.z, v.w);
    uint2* dst = (which == 0) ? reinterpret_cast<uint2*>(g_xh)
               : (which == 1) ? reinterpret_cast<uint2*>(g_w1h)
                              : reinterpret_cast<uint2*>(g_w2h);
    dst[i] = cvt.u;
}

// ---------------------------------------------------------------------------
// gate: scores, softmax, top-5, renorm; per-expert row lists + slot map
// ---------------------------------------------------------------------------
__global__ void gate_kernel(const float* __restrict__ x, const float* __restrict__ gw,
                            const float* __restrict__ gb) {
    int warp = (blockIdx.x * blockDim.x + threadIdx.x) >> 5;
    int lane = threadIdx.x & 31;
    if (warp >= B_ROWS) return;
    const float* xr = x + (size_t)warp * D_IN;
    float acc[NE];
#pragma unroll
    for (int e = 0; e < NE; e++) acc[e] = 0.f;
    for (int i = lane; i < D_IN; i += 32) {
        float xv = xr[i];
        const float* g = gw + i * NE;
#pragma unroll
        for (int e = 0; e < NE; e++) acc[e] += xv * g[e];
    }
#pragma unroll
    for (int e = 0; e < NE; e++)
#pragma unroll
        for (int off = 16; off > 0; off >>= 1)
            acc[e] += __shfl_xor_sync(0xffffffffu, acc[e], off);
    if (lane == 0) {
        const float invT = 0.36787944117144233f;
        float p[NE]; float mx = -1e30f;
#pragma unroll
        for (int e = 0; e < NE; e++) { p[e] = (acc[e] + gb[e]) * invT; mx = fmaxf(mx, p[e]); }
        float sum = 0.f;
#pragma unroll
        for (int e = 0; e < NE; e++) { p[e] = expf(p[e] - mx); sum += p[e]; }
        float inv = 1.f / sum;
#pragma unroll
        for (int e = 0; e < NE; e++) p[e] *= inv;
        bool sel[NE];
#pragma unroll
        for (int e = 0; e < NE; e++) sel[e] = false;
        for (int t = 0; t < NACT; t++) {
            int bi = -1; float bv = -1.f;
#pragma unroll
            for (int e = 0; e < NE; e++)
                if (!sel[e] && p[e] > bv) { bv = p[e]; bi = e; }
            sel[bi] = true;
        }
        float ws = 0.f;
#pragma unroll
        for (int e = 0; e < NE; e++) if (sel[e]) ws += p[e];
        float wi = 1.f / (ws + 1e-8f);
#pragma unroll
        for (int e = 0; e < NE; e++) {
            float wv = sel[e] ? p[e] * wi : 0.f;
            g_w[warp * NE + e] = wv;
            if (sel[e]) {
                int pos = atomicAdd(&g_cnt[e], 1);
                g_rows[e][pos] = warp;
                g_slot[warp * NE + e] = pos;
            }
        }
    }
}

// ---------------------------------------------------------------------------
// Row-gathered fp16 GEMM, CTA 256x128, 16 warps, BK=32, 2 stages.
// MODE 0: FFN1 -> g_hsh (scatter). MODE 1: FFN2 -> g_eo[e] (slot-contiguous).
// ---------------------------------------------------------------------------
template <int MODE>
__global__ void __launch_bounds__(512, 1) gemm_h(const float* __restrict__ b1) {
    extern __shared__ __align__(16) __half sm[];
    __shared__ int sidx[TM];

    const int tid  = threadIdx.x;
    const int z    = blockIdx.z;                        // expert
    const int row0 = blockIdx.y * TM;
    const int col0 = blockIdx.x * 128;

    const int cnt = g_cnt[z];
    if (row0 >= cnt) return;
    if (tid < TM) {
        int gr = row0 + tid;
        sidx[tid] = g_rows[z][gr < cnt ? gr : cnt - 1];
    }
    __syncthreads();

    const int    KT  = (MODE == 0) ? (D_IN / BK) : (D_H / BK);     // 32 / 128
    const size_t ldB = (MODE == 0) ? D_H : D_OUT;
    const __half* Ag = (MODE == 0) ? g_xh
                                   : g_hsh + (size_t)z * D_H;
    const __half* Bg = (MODE == 0) ? g_w1h + (size_t)z * D_IN * D_H + col0
                                   : g_w2h + (size_t)z * D_H * D_OUT + col0;

    wmma::fragment<wmma::accumulator, 16, 16, 16, float> c[4][2];
#pragma unroll
    for (int i = 0; i < 4; i++)
#pragma unroll
        for (int j = 0; j < 2; j++) wmma::fill_fragment(c[i][j], 0.f);

    auto load_stage = [&](int st, int k0) {
        __half* As = sm + st * STG_H;
        __half* Bs = As + ASTG_H;
#pragma unroll
        for (int f = tid; f < TM * 4; f += 512) {       // A: 256 rows x 4 segs
            int r = f >> 2, sg = f & 3;
            size_t arow = (MODE == 0) ? (size_t)sidx[r] * D_IN : (size_t)sidx[r] * EH;
            cp16h(&As[r * LDA + sg * 8], Ag + arow + k0 + sg * 8);
        }
#pragma unroll
        for (int f = tid; f < 512; f += 512) {          // B: 32 rows x 16 segs
            int r = f >> 4, sg = f & 15;
            cp16h(&Bs[r * LDB + sg * 8], Bg + (size_t)(k0 + r) * ldB + sg * 8);
        }
        CP_COMMIT();
    };

    const int wid = tid >> 5, lane = tid & 31;
    const int wm = wid >> 2;      // 0..3 (64-row block)
    const int wn = wid & 3;       // 0..3 (32-col block)

    load_stage(0, 0);
    for (int kt = 0; kt < KT; kt++) {
        CP_WAIT_ALL();
        __syncthreads();
        if (kt + 1 < KT) load_stage((kt + 1) & 1, (kt + 1) * BK);
        const __half* As = sm + (kt & 1) * STG_H;
        const __half* Bs = As + ASTG_H;
#pragma unroll
        for (int kk = 0; kk < BK; kk += 16) {
            wmma::fragment<wmma::matrix_a, 16, 16, 16, __half, wmma::row_major> a[4];
            wmma::fragment<wmma::matrix_b, 16, 16, 16, __half, wmma::row_major> b[2];
#pragma unroll
            for (int i = 0; i < 4; i++)
                wmma::load_matrix_sync(a[i], &As[(wm * 64 + i * 16) * LDA + kk], LDA);
#pragma unroll
            for (int j = 0; j < 2; j++)
                wmma::load_matrix_sync(b[j], &Bs[kk * LDB + wn * 32 + j * 16], LDB);
#pragma unroll
            for (int i = 0; i < 4; i++)
#pragma unroll
                for (int j = 0; j < 2; j++)
                    wmma::mma_sync(c[i][j], a[i], b[j], c[i][j]);
        }
    }
    __syncthreads();

    if (MODE == 0) {
        // Epilogue scratch overlaid on dead pipeline smem: 16x36 floats/warp (36KB)
        float* scw = reinterpret_cast<float*>(sm) + wid * (16 * 36);
        const float* b1e = b1 + (size_t)z * D_H;
#pragma unroll
        for (int i = 0; i < 4; i++) {
#pragma unroll
            for (int j = 0; j < 2; j++)
                wmma::store_matrix_sync(scw + j * 16, c[i][j], 36, wmma::mem_row_major);
            __syncwarp();
            int slot0 = wm * 64 + i * 16;
            int gc = col0 + wn * 32 + lane;
            float bv = b1e[gc];
#pragma unroll
            for (int r = 0; r < 16; r++) {
                int slot = slot0 + r;
                if (row0 + slot < cnt) {
                    int row = sidx[slot];
                    float v = fmaxf(scw[r * 36 + lane] + bv, 0.f) * g_w[row * NE + z];
                    g_hsh[(size_t)row * EH + (size_t)z * D_H + gc] = __float2half_rn(v);
                }
            }
            __syncwarp();
        }
    } else {
        float* Cg = g_eo + ((size_t)z * B_ROWS + row0) * D_OUT + col0;
#pragma unroll
        for (int i = 0; i < 4; i++)
#pragma unroll
            for (int j = 0; j < 2; j++)
                wmma::store_matrix_sync(&Cg[(size_t)(wm * 64 + i * 16) * D_OUT + wn * 32 + j * 16],
                                        c[i][j], D_OUT, wmma::mem_row_major);
    }
}

// ---------------------------------------------------------------------------
// finish: per row sum per-camp expert slots + weighted b2, PH epilogue.
// ---------------------------------------------------------------------------
__global__ void finish_kernel(const float* __restrict__ b2, const float* __restrict__ alpha,
                              const float* __restrict__ beta, float* __restrict__ out) {
    __shared__ __align__(16) float sb2[NE * D_OUT];
    __shared__ float sw[NE];
    __shared__ int   ssl[NE];
    __shared__ float red1[8], red2[8];
    __shared__ float sph;
    const int b = blockIdx.x, tid = threadIdx.x;
    for (int i = tid; i < NE * D_OUT; i += 256) sb2[i] = b2[i];
    if (tid < NE) {
        sw[tid]  = g_w[b * NE + tid];
        ssl[tid] = g_slot[b * NE + tid];
    }
    __syncthreads();
    const size_t SEC = (size_t)B_ROWS * D_OUT;
    float d[4]; float s1 = 0.f, s2 = 0.f;
#pragma unroll
    for (int t = 0; t < 4; t++) {
        int o = tid + 256 * t;
        float a = 0.f, g = 0.f;
#pragma unroll
        for (int e = 0; e < 4; e++) {
            if (sw[e] != 0.f)
                a += g_eo[((size_t)e * B_ROWS + ssl[e]) * D_OUT + o];
            a += sw[e] * sb2[e * D_OUT + o];
            if (sw[4 + e] != 0.f)
                g += g_eo[((size_t)(4 + e) * B_ROWS + ssl[4 + e]) * D_OUT + o];
            g += sw[4 + e] * sb2[(4 + e) * D_OUT + o];
        }
        out[SEC + (size_t)b * D_OUT + o] = a;
        out[2 * SEC + (size_t)b * D_OUT + o] = g;
        float dd = a - g; d[t] = dd; s1 += dd; s2 += dd * dd;
    }
#pragma unroll
    for (int off = 16; off > 0; off >>= 1) {
        s1 += __shfl_xor_sync(0xffffffffu, s1, off);
        s2 += __shfl_xor_sync(0xffffffffu, s2, off);
    }
    if ((tid & 31) == 0) { red1[tid >> 5] = s1; red2[tid >> 5] = s2; }
    __syncthreads();
    if (tid == 0) {
        float t1 = 0.f, t2 = 0.f;
#pragma unroll
        for (int w = 0; w < 8; w++) { t1 += red1[w]; t2 += red2[w]; }
        float l2 = sqrtf(t2);
        float mean = t1 * (1.f / D_OUT);
        float var = t2 * (1.f / D_OUT) - mean * mean;
        float zz = alpha[0] * (l2 * (1.f + var)) + beta[0];
        sph = 2.f / (1.f + expf(-zz));
    }
    __syncthreads();
    float ph = sph;
#pragma unroll
    for (int t = 0; t < 4; t++) {
        int o = tid + 256 * t;
        out[(size_t)b * D_OUT + o] = d[t] * ph;
    }
}

// ---------------------------------------------------------------------------
extern "C" void kernel_launch(void* const* d_in, const int* in_sizes, int n_in,
                              void* d_out, int out_size) {
    (void)in_sizes; (void)n_in; (void)out_size;
    const float* x  = (const float*)d_in[0];
    const float* gw = (const float*)d_in[1];
    const float* gb = (const float*)d_in[2];
    const float* w1 = (const float*)d_in[3];
    const float* b1 = (const float*)d_in[4];
    const float* w2 = (const float*)d_in[5];
    const float* b2 = (const float*)d_in[6];
    const float* pa = (const float*)d_in[7];
    const float* pb = (const float*)d_in[8];
    float* out = (float*)d_out;

    cudaFuncSetAttribute(gemm_h<0>, cudaFuncAttributeMaxDynamicSharedMemorySize, SMEM_BYTES);
    cudaFuncSetAttribute(gemm_h<1>, cudaFuncAttributeMaxDynamicSharedMemorySize, SMEM_BYTES);

    zero_cnt_kernel<<<1, 32>>>();
    gate_kernel<<<B_ROWS / 8, 256>>>(x, gw, gb);

    int n4x = (B_ROWS * D_IN) / 4;
    int n4w = (NE * D_IN * D_H) / 4;
    f2h_kernel<<<n4x / 256, 256>>>((const float4*)x, 0, n4x);
    f2h_kernel<<<n4w / 256, 256>>>((const float4*)w1, 1, n4w);
    f2h_kernel<<<n4w / 256, 256>>>((const float4*)w2, 2, n4w);

    gemm_h<0><<<dim3(D_H / 128, B_ROWS / TM, NE), 512, SMEM_BYTES>>>(b1);
    gemm_h<1><<<dim3(D_OUT / 128, B_ROWS / TM, NE), 512, SMEM_BYTES>>>(nullptr);
    finish_kernel<<<B_ROWS, 256>>>(b2, pa, pb, out);
}

// round 11
// speedup vs baseline: 1.2837x; 1.2837x over previous
#include <cuda_runtime.h>
#include <cuda_fp16.h>
#include <mma.h>
#include <cstdint>
#include <cstddef>

using namespace nvcuda;

#define B_ROWS 4096
#define D_IN   1024
#define D_H    4096
#define D_OUT  1024
#define NE     8
#define EH     32768
#define NACT   5

// GEMM tiling (R9 proven): CTA 128x128, 8 warps (2x4), warp 64x32, BK=64, 2 stages
#define BK  64
#define LDA 72     // A smem row stride in halves (144B)
#define LDB 136    // B smem row stride in halves (272B)
#define ASTG_H (128 * LDA)            // 9216 halves
#define BSTG_H (BK * LDB)             // 8704 halves
#define STG_H  (ASTG_H + BSTG_H)      // 17920 halves = 35840 B
#define SMEM_BYTES (2 * STG_H * 2)    // 71680 B

// Scratch (device globals; no allocation allowed)
__device__ float  g_w[B_ROWS * NE];
__device__ int    g_cnt[NE];
__device__ int    g_rows[NE][B_ROWS];
__device__ int    g_slot[B_ROWS * NE];
__device__ __half g_xh[(size_t)B_ROWS * D_IN];
__device__ __half g_w1h[(size_t)NE * D_IN * D_H];
__device__ __half g_w2h[(size_t)EH * D_OUT];
__device__ __half g_hsc[(size_t)NE * B_ROWS * D_H];    // 256 MB, slot-major compact
__device__ float  g_eo[(size_t)NE * B_ROWS * D_OUT];   // slot-indexed

// ---------------------------------------------------------------------------
__device__ __forceinline__ void cp16h(__half* sdst, const __half* gsrc) {
    uint32_t s = (uint32_t)__cvta_generic_to_shared(sdst);
    asm volatile("cp.async.cg.shared.global [%0], [%1], 16;\n" :: "r"(s), "l"(gsrc));
}
#define CP_COMMIT()   asm volatile("cp.async.commit_group;\n")
#define CP_WAIT_ALL() asm volatile("cp.async.wait_group 0;\n" ::: "memory")

// ---------------------------------------------------------------------------
__global__ void zero_cnt_kernel() {
    if (threadIdx.x < NE) g_cnt[threadIdx.x] = 0;
}

__global__ void f2h_kernel(const float4* __restrict__ src, int which, int n4) {
    int i = blockIdx.x * blockDim.x + threadIdx.x;
    if (i >= n4) return;
    float4 v = src[i];
    union { __half2 h2[2]; uint2 u; } cvt;
    cvt.h2[0] = __floats2half2_rn(v.x, v.y);
    cvt.h2[1] = __floats2half2_rn(v.z, v.w);
    uint2* dst = (which == 1) ? reinterpret_cast<uint2*>(g_w1h)
                              : reinterpret_cast<uint2*>(g_w2h);
    dst[i] = cvt.u;
}

// ---------------------------------------------------------------------------
// gate: scores, softmax, top-5, renorm; per-expert row lists + slot map.
// Also converts x -> g_xh (it touches every element anyway, coalesced).
// ---------------------------------------------------------------------------
__global__ void gate_kernel(const float* __restrict__ x, const float* __restrict__ gw,
                            const float* __restrict__ gb) {
    int warp = (blockIdx.x * blockDim.x + threadIdx.x) >> 5;
    int lane = threadIdx.x & 31;
    if (warp >= B_ROWS) return;
    const float* xr = x + (size_t)warp * D_IN;
    __half* xhr = g_xh + (size_t)warp * D_IN;
    float acc[NE];
#pragma unroll
    for (int e = 0; e < NE; e++) acc[e] = 0.f;
    for (int i = lane; i < D_IN; i += 32) {
        float xv = xr[i];
        xhr[i] = __float2half_rn(xv);
        const float* g = gw + i * NE;
#pragma unroll
        for (int e = 0; e < NE; e++) acc[e] += xv * g[e];
    }
#pragma unroll
    for (int e = 0; e < NE; e++)
#pragma unroll
        for (int off = 16; off > 0; off >>= 1)
            acc[e] += __shfl_xor_sync(0xffffffffu, acc[e], off);
    if (lane == 0) {
        const float invT = 0.36787944117144233f;
        float p[NE]; float mx = -1e30f;
#pragma unroll
        for (int e = 0; e < NE; e++) { p[e] = (acc[e] + gb[e]) * invT; mx = fmaxf(mx, p[e]); }
        float sum = 0.f;
#pragma unroll
        for (int e = 0; e < NE; e++) { p[e] = expf(p[e] - mx); sum += p[e]; }
        float inv = 1.f / sum;
#pragma unroll
        for (int e = 0; e < NE; e++) p[e] *= inv;
        bool sel[NE];
#pragma unroll
        for (int e = 0; e < NE; e++) sel[e] = false;
        for (int t = 0; t < NACT; t++) {
            int bi = -1; float bv = -1.f;
#pragma unroll
            for (int e = 0; e < NE; e++)
                if (!sel[e] && p[e] > bv) { bv = p[e]; bi = e; }
            sel[bi] = true;
        }
        float ws = 0.f;
#pragma unroll
        for (int e = 0; e < NE; e++) if (sel[e]) ws += p[e];
        float wi = 1.f / (ws + 1e-8f);
#pragma unroll
        for (int e = 0; e < NE; e++) {
            float wv = sel[e] ? p[e] * wi : 0.f;
            g_w[warp * NE + e] = wv;
            if (sel[e]) {
                int pos = atomicAdd(&g_cnt[e], 1);
                g_rows[e][pos] = warp;
                g_slot[warp * NE + e] = pos;
            }
        }
    }
}

// ---------------------------------------------------------------------------
// fp16 GEMM (R9 core), BK=64, 2-stage, 2 CTAs/SM.
// MODE 0: FFN1, A = gathered x rows -> g_hsc slot-major (contiguous writes)
// MODE 1: FFN2, A = g_hsc contiguous slot rows -> g_eo[e] (slot-contiguous)
// ---------------------------------------------------------------------------
template <int MODE>
__global__ void __launch_bounds__(256) gemm_h(const float* __restrict__ b1) {
    extern __shared__ __align__(16) __half sm[];
    __shared__ int sidx[128];

    const int tid  = threadIdx.x;
    const int z    = blockIdx.z;                        // expert
    const int row0 = blockIdx.y * 128;
    const int col0 = blockIdx.x * 128;

    const int cnt = g_cnt[z];
    if (row0 >= cnt) return;
    if (MODE == 0) {
        if (tid < 128) {
            int gr = row0 + tid;
            sidx[tid] = g_rows[z][gr < cnt ? gr : cnt - 1];
        }
        __syncthreads();
    }

    const int    KT  = (MODE == 0) ? (D_IN / BK) : (D_H / BK);     // 16 / 64
    const size_t ldB = (MODE == 0) ? D_H : D_OUT;
    const __half* Ag = (MODE == 0) ? g_xh
                                   : g_hsc + ((size_t)z * B_ROWS + row0) * D_H;
    const __half* Bg = (MODE == 0) ? g_w1h + (size_t)z * D_IN * D_H + col0
                                   : g_w2h + (size_t)z * D_H * D_OUT + col0;

    wmma::fragment<wmma::accumulator, 16, 16, 16, float> c[4][2];
#pragma unroll
    for (int i = 0; i < 4; i++)
#pragma unroll
        for (int j = 0; j < 2; j++) wmma::fill_fragment(c[i][j], 0.f);

    auto load_stage = [&](int st, int k0) {
        __half* As = sm + st * STG_H;
        __half* Bs = As + ASTG_H;
#pragma unroll
        for (int f = tid; f < 1024; f += 256) {         // A: 128 rows x 8 segs
            int r = f >> 3, sg = f & 7;
            size_t arow = (MODE == 0) ? (size_t)sidx[r] * D_IN : (size_t)r * D_H;
            cp16h(&As[r * LDA + sg * 8], Ag + arow + k0 + sg * 8);
        }
#pragma unroll
        for (int f = tid; f < 1024; f += 256) {         // B: 64 rows x 16 segs
            int r = f >> 4, sg = f & 15;
            cp16h(&Bs[r * LDB + sg * 8], Bg + (size_t)(k0 + r) * ldB + sg * 8);
        }
        CP_COMMIT();
    };

    const int wid = tid >> 5, lane = tid & 31;
    const int wm = wid >> 2;      // 0..1 (64-row block)
    const int wn = wid & 3;       // 0..3 (32-col block)

    load_stage(0, 0);
    for (int kt = 0; kt < KT; kt++) {
        CP_WAIT_ALL();
        __syncthreads();
        if (kt + 1 < KT) load_stage((kt + 1) & 1, (kt + 1) * BK);
        const __half* As = sm + (kt & 1) * STG_H;
        const __half* Bs = As + ASTG_H;
#pragma unroll
        for (int kk = 0; kk < BK; kk += 16) {
            wmma::fragment<wmma::matrix_a, 16, 16, 16, __half, wmma::row_major> a[4];
            wmma::fragment<wmma::matrix_b, 16, 16, 16, __half, wmma::row_major> b[2];
#pragma unroll
            for (int i = 0; i < 4; i++)
                wmma::load_matrix_sync(a[i], &As[(wm * 64 + i * 16) * LDA + kk], LDA);
#pragma unroll
            for (int j = 0; j < 2; j++)
                wmma::load_matrix_sync(b[j], &Bs[kk * LDB + wn * 32 + j * 16], LDB);
#pragma unroll
            for (int i = 0; i < 4; i++)
#pragma unroll
                for (int j = 0; j < 2; j++)
                    wmma::mma_sync(c[i][j], a[i], b[j], c[i][j]);
        }
    }
    __syncthreads();

    if (MODE == 0) {
        // Epilogue scratch overlaid on dead pipeline smem: 16x36 floats/warp
        float* scw = reinterpret_cast<float*>(sm) + wid * (16 * 36);
        const float* b1e = b1 + (size_t)z * D_H;
#pragma unroll
        for (int i = 0; i < 4; i++) {
#pragma unroll
            for (int j = 0; j < 2; j++)
                wmma::store_matrix_sync(scw + j * 16, c[i][j], 36, wmma::mem_row_major);
            __syncwarp();
            int slot0 = wm * 64 + i * 16;
            int gc = col0 + wn * 32 + lane;
            float bv = b1e[gc];
#pragma unroll
            for (int r = 0; r < 16; r++) {
                int slot = slot0 + r;                    // tile-local
                int gslot = row0 + slot;                 // global slot
                if (gslot < cnt) {
                    int row = sidx[slot];
                    float v = fmaxf(scw[r * 36 + lane] + bv, 0.f) * g_w[row * NE + z];
                    g_hsc[((size_t)z * B_ROWS + gslot) * D_H + gc] = __float2half_rn(v);
                }
            }
            __syncwarp();
        }
    } else {
        float* Cg = g_eo + ((size_t)z * B_ROWS + row0) * D_OUT + col0;
#pragma unroll
        for (int i = 0; i < 4; i++)
#pragma unroll
            for (int j = 0; j < 2; j++)
                wmma::store_matrix_sync(&Cg[(size_t)(wm * 64 + i * 16) * D_OUT + wn * 32 + j * 16],
                                        c[i][j], D_OUT, wmma::mem_row_major);
    }
}

// ---------------------------------------------------------------------------
// finish: per row sum per-camp expert slots + weighted b2, PH epilogue.
// ---------------------------------------------------------------------------
__global__ void finish_kernel(const float* __restrict__ b2, const float* __restrict__ alpha,
                              const float* __restrict__ beta, float* __restrict__ out) {
    __shared__ __align__(16) float sb2[NE * D_OUT];
    __shared__ float sw[NE];
    __shared__ int   ssl[NE];
    __shared__ float red1[8], red2[8];
    __shared__ float sph;
    const int b = blockIdx.x, tid = threadIdx.x;
    for (int i = tid; i < NE * D_OUT; i += 256) sb2[i] = b2[i];
    if (tid < NE) {
        sw[tid]  = g_w[b * NE + tid];
        ssl[tid] = g_slot[b * NE + tid];
    }
    __syncthreads();
    const size_t SEC = (size_t)B_ROWS * D_OUT;
    float d[4]; float s1 = 0.f, s2 = 0.f;
#pragma unroll
    for (int t = 0; t < 4; t++) {
        int o = tid + 256 * t;
        float a = 0.f, g = 0.f;
#pragma unroll
        for (int e = 0; e < 4; e++) {
            if (sw[e] != 0.f)
                a += g_eo[((size_t)e * B_ROWS + ssl[e]) * D_OUT + o];
            a += sw[e] * sb2[e * D_OUT + o];
            if (sw[4 + e] != 0.f)
                g += g_eo[((size_t)(4 + e) * B_ROWS + ssl[4 + e]) * D_OUT + o];
            g += sw[4 + e] * sb2[(4 + e) * D_OUT + o];
        }
        out[SEC + (size_t)b * D_OUT + o] = a;
        out[2 * SEC + (size_t)b * D_OUT + o] = g;
        float dd = a - g; d[t] = dd; s1 += dd; s2 += dd * dd;
    }
#pragma unroll
    for (int off = 16; off > 0; off >>= 1) {
        s1 += __shfl_xor_sync(0xffffffffu, s1, off);
        s2 += __shfl_xor_sync(0xffffffffu, s2, off);
    }
    if ((tid & 31) == 0) { red1[tid >> 5] = s1; red2[tid >> 5] = s2; }
    __syncthreads();
    if (tid == 0) {
        float t1 = 0.f, t2 = 0.f;
#pragma unroll
        for (int w = 0; w < 8; w++) { t1 += red1[w]; t2 += red2[w]; }
        float l2 = sqrtf(t2);
        float mean = t1 * (1.f / D_OUT);
        float var = t2 * (1.f / D_OUT) - mean * mean;
        float zz = alpha[0] * (l2 * (1.f + var)) + beta[0];
        sph = 2.f / (1.f + expf(-zz));
    }
    __syncthreads();
    float ph = sph;
#pragma unroll
    for (int t = 0; t < 4; t++) {
        int o = tid + 256 * t;
        out[(size_t)b * D_OUT + o] = d[t] * ph;
    }
}

// ---------------------------------------------------------------------------
extern "C" void kernel_launch(void* const* d_in, const int* in_sizes, int n_in,
                              void* d_out, int out_size) {
    (void)in_sizes; (void)n_in; (void)out_size;
    const float* x  = (const float*)d_in[0];
    const float* gw = (const float*)d_in[1];
    const float* gb = (const float*)d_in[2];
    const float* w1 = (const float*)d_in[3];
    const float* b1 = (const float*)d_in[4];
    const float* w2 = (const float*)d_in[5];
    const float* b2 = (const float*)d_in[6];
    const float* pa = (const float*)d_in[7];
    const float* pb = (const float*)d_in[8];
    float* out = (float*)d_out;

    cudaFuncSetAttribute(gemm_h<0>, cudaFuncAttributeMaxDynamicSharedMemorySize, SMEM_BYTES);
    cudaFuncSetAttribute(gemm_h<1>, cudaFuncAttributeMaxDynamicSharedMemorySize, SMEM_BYTES);

    zero_cnt_kernel<<<1, 32>>>();
    gate_kernel<<<B_ROWS / 8, 256>>>(x, gw, gb);

    int n4w = (NE * D_IN * D_H) / 4;
    f2h_kernel<<<n4w / 256, 256>>>((const float4*)w1, 1, n4w);
    f2h_kernel<<<n4w / 256, 256>>>((const float4*)w2, 2, n4w);

    gemm_h<0><<<dim3(D_H / 128, B_ROWS / 128, NE), 256, SMEM_BYTES>>>(b1);
    gemm_h<1><<<dim3(D_OUT / 128, B_ROWS / 128, NE), 256, SMEM_BYTES>>>(nullptr);
    finish_kernel<<<B_ROWS, 256>>>(b2, pa, pb, out);
}

// round 12
// speedup vs baseline: 1.3313x; 1.0371x over previous
#include <cuda_runtime.h>
#include <cuda_fp16.h>
#include <mma.h>
#include <cstdint>
#include <cstddef>

using namespace nvcuda;

#define B_ROWS 4096
#define D_IN   1024
#define D_H    4096
#define D_OUT  1024
#define NE     8
#define EH     32768
#define NACT   5

// GEMM tiling (R9 proven): CTA 128x128, 8 warps (2x4), warp 64x32, BK=64, 2 stages
#define BK  64
#define LDA 72     // A smem row stride in halves (144B)
#define LDB 136    // B smem row stride in halves (272B)
#define ASTG_H (128 * LDA)            // 9216 halves
#define BSTG_H (BK * LDB)             // 8704 halves
#define STG_H  (ASTG_H + BSTG_H)      // 17920 halves = 35840 B
#define SMEM_BYTES (2 * STG_H * 2)    // 71680 B

// Fused prep grid layout
#define GB_GATE 512                    // 512 blocks x 8 warps = 4096 rows
#define N4X     (B_ROWS * D_IN / 4)    // 1048576
#define N4W     (NE * D_IN * D_H / 4)  // 8388608
#define PB_X0   GB_GATE                         // 512
#define PB_W10  (PB_X0 + N4X / 256)             // 4608
#define PB_W20  (PB_W10 + N4W / 256)            // 37376
#define PB_END  (PB_W20 + N4W / 256)            // 70144

// Scratch (device globals; no allocation allowed)
__device__ float  g_w[B_ROWS * NE];
__device__ int    g_cnt[NE];
__device__ int    g_rows[NE][B_ROWS];
__device__ int    g_slot[B_ROWS * NE];
__device__ __half g_xh[(size_t)B_ROWS * D_IN];
__device__ __half g_w1h[(size_t)NE * D_IN * D_H];
__device__ __half g_w2h[(size_t)EH * D_OUT];
__device__ __half g_hsh[(size_t)B_ROWS * EH];
__device__ float  g_eo[(size_t)NE * B_ROWS * D_OUT];   // slot-indexed

// ---------------------------------------------------------------------------
__device__ __forceinline__ void cp16h(__half* sdst, const __half* gsrc) {
    uint32_t s = (uint32_t)__cvta_generic_to_shared(sdst);
    asm volatile("cp.async.cg.shared.global [%0], [%1], 16;\n" :: "r"(s), "l"(gsrc));
}
#define CP_COMMIT()   asm volatile("cp.async.commit_group;\n")
#define CP_WAIT_ALL() asm volatile("cp.async.wait_group 0;\n" ::: "memory")

// ---------------------------------------------------------------------------
// Fused prep: gate (blocks [0,GB_GATE)) + x/w1/w2 fp32->fp16 conversions.
// All parts independent; one launch lets the GPU overlap them.
// ---------------------------------------------------------------------------
__global__ void prep_kernel(const float* __restrict__ x, const float* __restrict__ gw,
                            const float* __restrict__ gb,
                            const float4* __restrict__ w1f4,
                            const float4* __restrict__ w2f4) {
    const int b = blockIdx.x;
    const int tid = threadIdx.x;

    if (b >= GB_GATE) {
        // Conversion section
        const float4* src; uint2* dst; int i;
        if (b < PB_W10)      { src = (const float4*)x; dst = (uint2*)g_xh;  i = (b - PB_X0) * 256 + tid; }
        else if (b < PB_W20) { src = w1f4;             dst = (uint2*)g_w1h; i = (b - PB_W10) * 256 + tid; }
        else                 { src = w2f4;             dst = (uint2*)g_w2h; i = (b - PB_W20) * 256 + tid; }
        float4 v = src[i];
        union { __half2 h2[2]; uint2 u; } cvt;
        cvt.h2[0] = __floats2half2_rn(v.x, v.y);
        cvt.h2[1] = __floats2half2_rn(v.z, v.w);
        dst[i] = cvt.u;
        return;
    }

    // Gate section: one warp per row (proven R9 gate)
    int warp = (b * 256 + tid) >> 5;
    int lane = tid & 31;
    const float* xr = x + (size_t)warp * D_IN;
    float acc[NE];
#pragma unroll
    for (int e = 0; e < NE; e++) acc[e] = 0.f;
    for (int i = lane; i < D_IN; i += 32) {
        float xv = xr[i];
        const float* g = gw + i * NE;
#pragma unroll
        for (int e = 0; e < NE; e++) acc[e] += xv * g[e];
    }
#pragma unroll
    for (int e = 0; e < NE; e++)
#pragma unroll
        for (int off = 16; off > 0; off >>= 1)
            acc[e] += __shfl_xor_sync(0xffffffffu, acc[e], off);
    if (lane == 0) {
        const float invT = 0.36787944117144233f;
        float p[NE]; float mx = -1e30f;
#pragma unroll
        for (int e = 0; e < NE; e++) { p[e] = (acc[e] + gb[e]) * invT; mx = fmaxf(mx, p[e]); }
        float sum = 0.f;
#pragma unroll
        for (int e = 0; e < NE; e++) { p[e] = expf(p[e] - mx); sum += p[e]; }
        float inv = 1.f / sum;
#pragma unroll
        for (int e = 0; e < NE; e++) p[e] *= inv;
        bool sel[NE];
#pragma unroll
        for (int e = 0; e < NE; e++) sel[e] = false;
        for (int t = 0; t < NACT; t++) {
            int bi = -1; float bv = -1.f;
#pragma unroll
            for (int e = 0; e < NE; e++)
                if (!sel[e] && p[e] > bv) { bv = p[e]; bi = e; }
            sel[bi] = true;
        }
        float ws = 0.f;
#pragma unroll
        for (int e = 0; e < NE; e++) if (sel[e]) ws += p[e];
        float wi = 1.f / (ws + 1e-8f);
#pragma unroll
        for (int e = 0; e < NE; e++) {
            float wv = sel[e] ? p[e] * wi : 0.f;
            g_w[warp * NE + e] = wv;
            if (sel[e]) {
                int pos = atomicAdd(&g_cnt[e], 1);
                g_rows[e][pos] = warp;
                g_slot[warp * NE + e] = pos;
            }
        }
    }
}

// ---------------------------------------------------------------------------
// Row-gathered fp16 GEMM (R9 core, verbatim), BK=64, 2-stage, 2 CTAs/SM.
// MODE 0: FFN1 -> g_hsh (scatter). MODE 1: FFN2 -> g_eo[e] (slot-contiguous).
// ---------------------------------------------------------------------------
template <int MODE>
__global__ void __launch_bounds__(256) gemm_h(const float* __restrict__ b1) {
    extern __shared__ __align__(16) __half sm[];
    __shared__ int sidx[128];

    const int tid  = threadIdx.x;
    const int z    = blockIdx.z;                        // expert
    const int row0 = blockIdx.y * 128;
    const int col0 = blockIdx.x * 128;

    const int cnt = g_cnt[z];
    if (row0 >= cnt) return;
    if (tid < 128) {
        int gr = row0 + tid;
        sidx[tid] = g_rows[z][gr < cnt ? gr : cnt - 1];
    }
    __syncthreads();

    const int    KT  = (MODE == 0) ? (D_IN / BK) : (D_H / BK);     // 16 / 64
    const size_t ldB = (MODE == 0) ? D_H : D_OUT;
    const __half* Ag = (MODE == 0) ? g_xh
                                   : g_hsh + (size_t)z * D_H;
    const __half* Bg = (MODE == 0) ? g_w1h + (size_t)z * D_IN * D_H + col0
                                   : g_w2h + (size_t)z * D_H * D_OUT + col0;

    wmma::fragment<wmma::accumulator, 16, 16, 16, float> c[4][2];
#pragma unroll
    for (int i = 0; i < 4; i++)
#pragma unroll
        for (int j = 0; j < 2; j++) wmma::fill_fragment(c[i][j], 0.f);

    auto load_stage = [&](int st, int k0) {
        __half* As = sm + st * STG_H;
        __half* Bs = As + ASTG_H;
#pragma unroll
        for (int f = tid; f < 1024; f += 256) {         // A: 128 rows x 8 segs
            int r = f >> 3, sg = f & 7;
            size_t arow = (MODE == 0) ? (size_t)sidx[r] * D_IN : (size_t)sidx[r] * EH;
            cp16h(&As[r * LDA + sg * 8], Ag + arow + k0 + sg * 8);
        }
#pragma unroll
        for (int f = tid; f < 1024; f += 256) {         // B: 64 rows x 16 segs
            int r = f >> 4, sg = f & 15;
            cp16h(&Bs[r * LDB + sg * 8], Bg + (size_t)(k0 + r) * ldB + sg * 8);
        }
        CP_COMMIT();
    };

    const int wid = tid >> 5, lane = tid & 31;
    const int wm = wid >> 2;      // 0..1 (64-row block)
    const int wn = wid & 3;       // 0..3 (32-col block)

    load_stage(0, 0);
    for (int kt = 0; kt < KT; kt++) {
        CP_WAIT_ALL();
        __syncthreads();
        if (kt + 1 < KT) load_stage((kt + 1) & 1, (kt + 1) * BK);
        const __half* As = sm + (kt & 1) * STG_H;
        const __half* Bs = As + ASTG_H;
#pragma unroll
        for (int kk = 0; kk < BK; kk += 16) {
            wmma::fragment<wmma::matrix_a, 16, 16, 16, __half, wmma::row_major> a[4];
            wmma::fragment<wmma::matrix_b, 16, 16, 16, __half, wmma::row_major> b[2];
#pragma unroll
            for (int i = 0; i < 4; i++)
                wmma::load_matrix_sync(a[i], &As[(wm * 64 + i * 16) * LDA + kk], LDA);
#pragma unroll
            for (int j = 0; j < 2; j++)
                wmma::load_matrix_sync(b[j], &Bs[kk * LDB + wn * 32 + j * 16], LDB);
#pragma unroll
            for (int i = 0; i < 4; i++)
#pragma unroll
                for (int j = 0; j < 2; j++)
                    wmma::mma_sync(c[i][j], a[i], b[j], c[i][j]);
        }
    }
    __syncthreads();

    if (MODE == 0) {
        // Epilogue scratch overlaid on dead pipeline smem: 16x36 floats/warp
        float* scw = reinterpret_cast<float*>(sm) + wid * (16 * 36);
        const float* b1e = b1 + (size_t)z * D_H;
#pragma unroll
        for (int i = 0; i < 4; i++) {
#pragma unroll
            for (int j = 0; j < 2; j++)
                wmma::store_matrix_sync(scw + j * 16, c[i][j], 36, wmma::mem_row_major);
            __syncwarp();
            int slot0 = wm * 64 + i * 16;
            int gc = col0 + wn * 32 + lane;
            float bv = b1e[gc];
#pragma unroll
            for (int r = 0; r < 16; r++) {
                int slot = slot0 + r;
                if (row0 + slot < cnt) {
                    int row = sidx[slot];
                    float v = fmaxf(scw[r * 36 + lane] + bv, 0.f) * g_w[row * NE + z];
                    g_hsh[(size_t)row * EH + (size_t)z * D_H + gc] = __float2half_rn(v);
                }
            }
            __syncwarp();
        }
    } else {
        float* Cg = g_eo + ((size_t)z * B_ROWS + row0) * D_OUT + col0;
#pragma unroll
        for (int i = 0; i < 4; i++)
#pragma unroll
            for (int j = 0; j < 2; j++)
                wmma::store_matrix_sync(&Cg[(size_t)(wm * 64 + i * 16) * D_OUT + wn * 32 + j * 16],
                                        c[i][j], D_OUT, wmma::mem_row_major);
    }
}

// ---------------------------------------------------------------------------
// finish (R9 verbatim): per row sum per-camp expert slots + weighted b2, PH.
// ---------------------------------------------------------------------------
__global__ void finish_kernel(const float* __restrict__ b2, const float* __restrict__ alpha,
                              const float* __restrict__ beta, float* __restrict__ out) {
    __shared__ __align__(16) float sb2[NE * D_OUT];
    __shared__ float sw[NE];
    __shared__ int   ssl[NE];
    __shared__ float red1[8], red2[8];
    __shared__ float sph;
    const int b = blockIdx.x, tid = threadIdx.x;
    for (int i = tid; i < NE * D_OUT; i += 256) sb2[i] = b2[i];
    if (tid < NE) {
        sw[tid]  = g_w[b * NE + tid];
        ssl[tid] = g_slot[b * NE + tid];
    }
    __syncthreads();
    const size_t SEC = (size_t)B_ROWS * D_OUT;
    float d[4]; float s1 = 0.f, s2 = 0.f;
#pragma unroll
    for (int t = 0; t < 4; t++) {
        int o = tid + 256 * t;
        float a = 0.f, g = 0.f;
#pragma unroll
        for (int e = 0; e < 4; e++) {
            if (sw[e] != 0.f)
                a += g_eo[((size_t)e * B_ROWS + ssl[e]) * D_OUT + o];
            a += sw[e] * sb2[e * D_OUT + o];
            if (sw[4 + e] != 0.f)
                g += g_eo[((size_t)(4 + e) * B_ROWS + ssl[4 + e]) * D_OUT + o];
            g += sw[4 + e] * sb2[(4 + e) * D_OUT + o];
        }
        out[SEC + (size_t)b * D_OUT + o] = a;
        out[2 * SEC + (size_t)b * D_OUT + o] = g;
        float dd = a - g; d[t] = dd; s1 += dd; s2 += dd * dd;
    }
#pragma unroll
    for (int off = 16; off > 0; off >>= 1) {
        s1 += __shfl_xor_sync(0xffffffffu, s1, off);
        s2 += __shfl_xor_sync(0xffffffffu, s2, off);
    }
    if ((tid & 31) == 0) { red1[tid >> 5] = s1; red2[tid >> 5] = s2; }
    __syncthreads();
    if (tid == 0) {
        float t1 = 0.f, t2 = 0.f;
#pragma unroll
        for (int w = 0; w < 8; w++) { t1 += red1[w]; t2 += red2[w]; }
        float l2 = sqrtf(t2);
        float mean = t1 * (1.f / D_OUT);
        float var = t2 * (1.f / D_OUT) - mean * mean;
        float zz = alpha[0] * (l2 * (1.f + var)) + beta[0];
        sph = 2.f / (1.f + expf(-zz));
    }
    __syncthreads();
    float ph = sph;
#pragma unroll
    for (int t = 0; t < 4; t++) {
        int o = tid + 256 * t;
        out[(size_t)b * D_OUT + o] = d[t] * ph;
    }
}

// ---------------------------------------------------------------------------
extern "C" void kernel_launch(void* const* d_in, const int* in_sizes, int n_in,
                              void* d_out, int out_size) {
    (void)in_sizes; (void)n_in; (void)out_size;
    const float* x  = (const float*)d_in[0];
    const float* gw = (const float*)d_in[1];
    const float* gb = (const float*)d_in[2];
    const float* w1 = (const float*)d_in[3];
    const float* b1 = (const float*)d_in[4];
    const float* w2 = (const float*)d_in[5];
    const float* b2 = (const float*)d_in[6];
    const float* pa = (const float*)d_in[7];
    const float* pb = (const float*)d_in[8];
    float* out = (float*)d_out;

    cudaFuncSetAttribute(gemm_h<0>, cudaFuncAttributeMaxDynamicSharedMemorySize, SMEM_BYTES);
    cudaFuncSetAttribute(gemm_h<1>, cudaFuncAttributeMaxDynamicSharedMemorySize, SMEM_BYTES);

    void* cnt_ptr = nullptr;
    cudaGetSymbolAddress(&cnt_ptr, g_cnt);
    cudaMemsetAsync(cnt_ptr, 0, NE * sizeof(int));

    prep_kernel<<<PB_END, 256>>>(x, gw, gb, (const float4*)w1, (const float4*)w2);

    gemm_h<0><<<dim3(D_H / 128, B_ROWS / 128, NE), 256, SMEM_BYTES>>>(b1);
    gemm_h<1><<<dim3(D_OUT / 128, B_ROWS / 128, NE), 256, SMEM_BYTES>>>(nullptr);
    finish_kernel<<<B_ROWS, 256>>>(b2, pa, pb, out);
}

// round 13
// speedup vs baseline: 1.3373x; 1.0045x over previous
#include <cuda_runtime.h>
#include <cuda_fp16.h>
#include <mma.h>
#include <cstdint>
#include <cstddef>

using namespace nvcuda;

#define B_ROWS 4096
#define D_IN   1024
#define D_H    4096
#define D_OUT  1024
#define NE     8
#define EH     32768
#define NACT   5

// GEMM tiling (proven): CTA 128x128, 8 warps (2x4), warp 64x32, BK=64, 2 stages
#define BK  64
#define LDA 72     // A smem row stride in halves (144B)
#define LDB 136    // B smem row stride in halves (272B)
#define ASTG_H (128 * LDA)            // 9216 halves
#define BSTG_H (BK * LDB)             // 8704 halves
#define STG_H  (ASTG_H + BSTG_H)      // 17920 halves = 35840 B
#define SMEM_BYTES (2 * STG_H * 2)    // 71680 B

// Fused prep grid layout: gate + x + w1 (w2 converts inside GEMM1's launch)
#define GB_GATE 512                    // 512 blocks x 8 warps = 4096 rows
#define N4X     (B_ROWS * D_IN / 4)    // 1048576
#define N4W     (NE * D_IN * D_H / 4)  // 8388608
#define PB_X0   GB_GATE                         // 512
#define PB_W10  (PB_X0 + N4X / 256)             // 4608
#define PB_END  (PB_W10 + N4W / 256)            // 37376

// Scratch (device globals; no allocation allowed)
__device__ float  g_w[B_ROWS * NE];
__device__ int    g_cnt[NE];
__device__ int    g_rows[NE][B_ROWS];
__device__ int    g_slot[B_ROWS * NE];
__device__ __half g_xh[(size_t)B_ROWS * D_IN];
__device__ __half g_w1h[(size_t)NE * D_IN * D_H];
__device__ __half g_w2h[(size_t)EH * D_OUT];
__device__ __half g_hsh[(size_t)B_ROWS * EH];
__device__ float  g_eo[(size_t)NE * B_ROWS * D_OUT];   // slot-indexed, incl. w*b2

// ---------------------------------------------------------------------------
__device__ __forceinline__ void cp16h(__half* sdst, const __half* gsrc) {
    uint32_t s = (uint32_t)__cvta_generic_to_shared(sdst);
    asm volatile("cp.async.cg.shared.global [%0], [%1], 16;\n" :: "r"(s), "l"(gsrc));
}
#define CP_COMMIT()   asm volatile("cp.async.commit_group;\n")
#define CP_WAIT_ALL() asm volatile("cp.async.wait_group 0;\n" ::: "memory")

__device__ __forceinline__ void cvt_f4(const float4* __restrict__ src,
                                       uint2* __restrict__ dst, int i) {
    float4 v = src[i];
    union { __half2 h2[2]; uint2 u; } cvt;
    cvt.h2[0] = __floats2half2_rn(v.x, v.y);
    cvt.h2[1] = __floats2half2_rn(v.z, v.w);
    dst[i] = cvt.u;
}

// ---------------------------------------------------------------------------
// Fused prep: gate (blocks [0,GB_GATE)) + x/w1 fp32->fp16 conversions.
// ---------------------------------------------------------------------------
__global__ void prep_kernel(const float* __restrict__ x, const float* __restrict__ gw,
                            const float* __restrict__ gb,
                            const float4* __restrict__ w1f4) {
    const int b = blockIdx.x;
    const int tid = threadIdx.x;

    if (b >= GB_GATE) {
        if (b < PB_W10) cvt_f4((const float4*)x, (uint2*)g_xh, (b - PB_X0) * 256 + tid);
        else            cvt_f4(w1f4, (uint2*)g_w1h, (b - PB_W10) * 256 + tid);
        return;
    }

    // Gate section: one warp per row (proven)
    int warp = (b * 256 + tid) >> 5;
    int lane = tid & 31;
    const float* xr = x + (size_t)warp * D_IN;
    float acc[NE];
#pragma unroll
    for (int e = 0; e < NE; e++) acc[e] = 0.f;
    for (int i = lane; i < D_IN; i += 32) {
        float xv = xr[i];
        const float* g = gw + i * NE;
#pragma unroll
        for (int e = 0; e < NE; e++) acc[e] += xv * g[e];
    }
#pragma unroll
    for (int e = 0; e < NE; e++)
#pragma unroll
        for (int off = 16; off > 0; off >>= 1)
            acc[e] += __shfl_xor_sync(0xffffffffu, acc[e], off);
    if (lane == 0) {
        const float invT = 0.36787944117144233f;
        float p[NE]; float mx = -1e30f;
#pragma unroll
        for (int e = 0; e < NE; e++) { p[e] = (acc[e] + gb[e]) * invT; mx = fmaxf(mx, p[e]); }
        float sum = 0.f;
#pragma unroll
        for (int e = 0; e < NE; e++) { p[e] = expf(p[e] - mx); sum += p[e]; }
        float inv = 1.f / sum;
#pragma unroll
        for (int e = 0; e < NE; e++) p[e] *= inv;
        bool sel[NE];
#pragma unroll
        for (int e = 0; e < NE; e++) sel[e] = false;
        for (int t = 0; t < NACT; t++) {
            int bi = -1; float bv = -1.f;
#pragma unroll
            for (int e = 0; e < NE; e++)
                if (!sel[e] && p[e] > bv) { bv = p[e]; bi = e; }
            sel[bi] = true;
        }
        float ws = 0.f;
#pragma unroll
        for (int e = 0; e < NE; e++) if (sel[e]) ws += p[e];
        float wi = 1.f / (ws + 1e-8f);
#pragma unroll
        for (int e = 0; e < NE; e++) {
            float wv = sel[e] ? p[e] * wi : 0.f;
            g_w[warp * NE + e] = wv;
            if (sel[e]) {
                int pos = atomicAdd(&g_cnt[e], 1);
                g_rows[e][pos] = warp;
                g_slot[warp * NE + e] = pos;
            }
        }
    }
}

// ---------------------------------------------------------------------------
// Row-gathered fp16 GEMM (proven core), BK=64, 2-stage, 2 CTAs/SM.
// MODE 0: FFN1 -> g_hsh (scatter); extra z-slice (z==NE) converts w2.
// MODE 1: FFN2 -> g_eo[e] (slot-contiguous), epilogue adds w*b2.
// ---------------------------------------------------------------------------
template <int MODE>
__global__ void __launch_bounds__(256) gemm_h(const float* __restrict__ bias,
                                              const float4* __restrict__ w2f4) {
    extern __shared__ __align__(16) __half sm[];
    __shared__ int sidx[128];

    const int tid  = threadIdx.x;
    const int z    = blockIdx.z;                        // expert (or NE = w2 convert)
    const int row0 = blockIdx.y * 128;
    const int col0 = blockIdx.x * 128;

    if (MODE == 0 && z == NE) {
        // w2 fp32->fp16 conversion, hidden under GEMM1: 1024 blocks x 256 thr x 32 f4
        int bid = blockIdx.y * gridDim.x + blockIdx.x;  // 0..1023
        int base = bid * 256 + tid;
#pragma unroll
        for (int k = 0; k < 32; k++)
            cvt_f4(w2f4, (uint2*)g_w2h, base + k * 262144);
        return;
    }

    const int cnt = g_cnt[z];
    if (row0 >= cnt) return;
    if (tid < 128) {
        int gr = row0 + tid;
        sidx[tid] = g_rows[z][gr < cnt ? gr : cnt - 1];
    }
    __syncthreads();

    const int    KT  = (MODE == 0) ? (D_IN / BK) : (D_H / BK);     // 16 / 64
    const size_t ldB = (MODE == 0) ? D_H : D_OUT;
    const __half* Ag = (MODE == 0) ? g_xh
                                   : g_hsh + (size_t)z * D_H;
    const __half* Bg = (MODE == 0) ? g_w1h + (size_t)z * D_IN * D_H + col0
                                   : g_w2h + (size_t)z * D_H * D_OUT + col0;

    wmma::fragment<wmma::accumulator, 16, 16, 16, float> c[4][2];
#pragma unroll
    for (int i = 0; i < 4; i++)
#pragma unroll
        for (int j = 0; j < 2; j++) wmma::fill_fragment(c[i][j], 0.f);

    auto load_stage = [&](int st, int k0) {
        __half* As = sm + st * STG_H;
        __half* Bs = As + ASTG_H;
#pragma unroll
        for (int f = tid; f < 1024; f += 256) {         // A: 128 rows x 8 segs
            int r = f >> 3, sg = f & 7;
            size_t arow = (MODE == 0) ? (size_t)sidx[r] * D_IN : (size_t)sidx[r] * EH;
            cp16h(&As[r * LDA + sg * 8], Ag + arow + k0 + sg * 8);
        }
#pragma unroll
        for (int f = tid; f < 1024; f += 256) {         // B: 64 rows x 16 segs
            int r = f >> 4, sg = f & 15;
            cp16h(&Bs[r * LDB + sg * 8], Bg + (size_t)(k0 + r) * ldB + sg * 8);
        }
        CP_COMMIT();
    };

    const int wid = tid >> 5, lane = tid & 31;
    const int wm = wid >> 2;      // 0..1 (64-row block)
    const int wn = wid & 3;       // 0..3 (32-col block)

    load_stage(0, 0);
    for (int kt = 0; kt < KT; kt++) {
        CP_WAIT_ALL();
        __syncthreads();
        if (kt + 1 < KT) load_stage((kt + 1) & 1, (kt + 1) * BK);
        const __half* As = sm + (kt & 1) * STG_H;
        const __half* Bs = As + ASTG_H;
#pragma unroll
        for (int kk = 0; kk < BK; kk += 16) {
            wmma::fragment<wmma::matrix_a, 16, 16, 16, __half, wmma::row_major> a[4];
            wmma::fragment<wmma::matrix_b, 16, 16, 16, __half, wmma::row_major> b[2];
#pragma unroll
            for (int i = 0; i < 4; i++)
                wmma::load_matrix_sync(a[i], &As[(wm * 64 + i * 16) * LDA + kk], LDA);
#pragma unroll
            for (int j = 0; j < 2; j++)
                wmma::load_matrix_sync(b[j], &Bs[kk * LDB + wn * 32 + j * 16], LDB);
#pragma unroll
            for (int i = 0; i < 4; i++)
#pragma unroll
                for (int j = 0; j < 2; j++)
                    wmma::mma_sync(c[i][j], a[i], b[j], c[i][j]);
        }
    }
    __syncthreads();

    // Epilogue: stage fragments via per-warp smem scratch (dead pipeline smem)
    float* scw = reinterpret_cast<float*>(sm) + wid * (16 * 36);
    const int gc = col0 + wn * 32 + lane;               // 32 cols per warp
    const float bv = bias[(size_t)z * (MODE == 0 ? D_H : D_OUT) + gc];

#pragma unroll
    for (int i = 0; i < 4; i++) {
#pragma unroll
        for (int j = 0; j < 2; j++)
            wmma::store_matrix_sync(scw + j * 16, c[i][j], 36, wmma::mem_row_major);
        __syncwarp();
        int slot0 = wm * 64 + i * 16;
#pragma unroll
        for (int r = 0; r < 16; r++) {
            int slot = slot0 + r;
            int gslot = row0 + slot;
            int row = sidx[slot];
            float wv = g_w[row * NE + z];
            if (MODE == 0) {
                if (gslot < cnt) {
                    float v = fmaxf(scw[r * 36 + lane] + bv, 0.f) * wv;
                    g_hsh[(size_t)row * EH + (size_t)z * D_H + gc] = __float2half_rn(v);
                }
            } else {
                // g_eo = w*(h@w2) + w*b2 (hs already carries w); garbage slots unread
                g_eo[((size_t)z * B_ROWS + gslot) * D_OUT + gc] =
                    scw[r * 36 + lane] + wv * bv;
            }
        }
        __syncwarp();
    }
}

// ---------------------------------------------------------------------------
// finish: per row sum per-camp expert slots (b2 already folded), PH epilogue.
// ---------------------------------------------------------------------------
__global__ void finish_kernel(const float* __restrict__ alpha,
                              const float* __restrict__ beta, float* __restrict__ out) {
    __shared__ float sw[NE];
    __shared__ int   ssl[NE];
    __shared__ float red1[8], red2[8];
    __shared__ float sph;
    const int b = blockIdx.x, tid = threadIdx.x;
    if (tid < NE) {
        sw[tid]  = g_w[b * NE + tid];
        ssl[tid] = g_slot[b * NE + tid];
    }
    __syncthreads();
    const size_t SEC = (size_t)B_ROWS * D_OUT;
    float d[4]; float s1 = 0.f, s2 = 0.f;
#pragma unroll
    for (int t = 0; t < 4; t++) {
        int o = tid + 256 * t;
        float a = 0.f, g = 0.f;
#pragma unroll
        for (int e = 0; e < 4; e++) {
            if (sw[e] != 0.f)
                a += g_eo[((size_t)e * B_ROWS + ssl[e]) * D_OUT + o];
            if (sw[4 + e] != 0.f)
                g += g_eo[((size_t)(4 + e) * B_ROWS + ssl[4 + e]) * D_OUT + o];
        }
        out[SEC + (size_t)b * D_OUT + o] = a;
        out[2 * SEC + (size_t)b * D_OUT + o] = g;
        float dd = a - g; d[t] = dd; s1 += dd; s2 += dd * dd;
    }
#pragma unroll
    for (int off = 16; off > 0; off >>= 1) {
        s1 += __shfl_xor_sync(0xffffffffu, s1, off);
        s2 += __shfl_xor_sync(0xffffffffu, s2, off);
    }
    if ((tid & 31) == 0) { red1[tid >> 5] = s1; red2[tid >> 5] = s2; }
    __syncthreads();
    if (tid == 0) {
        float t1 = 0.f, t2 = 0.f;
#pragma unroll
        for (int w = 0; w < 8; w++) { t1 += red1[w]; t2 += red2[w]; }
        float l2 = sqrtf(t2);
        float mean = t1 * (1.f / D_OUT);
        float var = t2 * (1.f / D_OUT) - mean * mean;
        float zz = alpha[0] * (l2 * (1.f + var)) + beta[0];
        sph = 2.f / (1.f + expf(-zz));
    }
    __syncthreads();
    float ph = sph;
#pragma unroll
    for (int t = 0; t < 4; t++) {
        int o = tid + 256 * t;
        out[(size_t)b * D_OUT + o] = d[t] * ph;
    }
}

// ---------------------------------------------------------------------------
extern "C" void kernel_launch(void* const* d_in, const int* in_sizes, int n_in,
                              void* d_out, int out_size) {
    (void)in_sizes; (void)n_in; (void)out_size;
    const float* x  = (const float*)d_in[0];
    const float* gw = (const float*)d_in[1];
    const float* gb = (const float*)d_in[2];
    const float* w1 = (const float*)d_in[3];
    const float* b1 = (const float*)d_in[4];
    const float* w2 = (const float*)d_in[5];
    const float* b2 = (const float*)d_in[6];
    const float* pa = (const float*)d_in[7];
    const float* pb = (const float*)d_in[8];
    float* out = (float*)d_out;

    cudaFuncSetAttribute(gemm_h<0>, cudaFuncAttributeMaxDynamicSharedMemorySize, SMEM_BYTES);
    cudaFuncSetAttribute(gemm_h<1>, cudaFuncAttributeMaxDynamicSharedMemorySize, SMEM_BYTES);

    void* cnt_ptr = nullptr;
    cudaGetSymbolAddress(&cnt_ptr, g_cnt);
    cudaMemsetAsync(cnt_ptr, 0, NE * sizeof(int));

    prep_kernel<<<PB_END, 256>>>(x, gw, gb, (const float4*)w1);

    // GEMM1 (+ w2 conversion in z==NE slice)
    gemm_h<0><<<dim3(D_H / 128, B_ROWS / 128, NE + 1), 256, SMEM_BYTES>>>(b1, (const float4*)w2);
    // GEMM2 (b2 folded into epilogue)
    gemm_h<1><<<dim3(D_OUT / 128, B_ROWS / 128, NE), 256, SMEM_BYTES>>>(b2, nullptr);
    finish_kernel<<<B_ROWS, 256>>>(pa, pb, out);
}

// round 15
// speedup vs baseline: 1.3728x; 1.0266x over previous
#include <cuda_runtime.h>
#include <cuda_fp16.h>
#include <mma.h>
#include <cstdint>
#include <cstddef>

using namespace nvcuda;

#define B_ROWS 4096
#define D_IN   1024
#define D_H    4096
#define D_OUT  1024
#define NE     8
#define EH     32768
#define NACT   5

// GEMM tiling: CTA 128x128, 4 warps (2x2), warp tile 64x64, BK=64, 2 stages
#define BK  64
#define LDA 72     // A smem row stride in halves (144B)
#define LDB 136    // B smem row stride in halves (272B)
#define ASTG_H (128 * LDA)            // 9216 halves
#define BSTG_H (BK * LDB)             // 8704 halves
#define STG_H  (ASTG_H + BSTG_H)      // 17920 halves = 35840 B
#define SMEM_BYTES (2 * STG_H * 2)    // 71680 B (2 CTAs/SM)

// Fused prep grid layout: gate + x + w1 (w2 converts inside GEMM1's launch)
#define GB_GATE 512
#define N4X     (B_ROWS * D_IN / 4)    // 1048576
#define N4W     (NE * D_IN * D_H / 4)  // 8388608
#define PB_X0   GB_GATE
#define PB_W10  (PB_X0 + N4X / 256)    // 4608
#define PB_END  (PB_W10 + N4W / 256)   // 37376

// Scratch (device globals; no allocation allowed)
__device__ float  g_w[B_ROWS * NE];
__device__ int    g_cnt[NE];
__device__ int    g_rows[NE][B_ROWS];
__device__ int    g_slot[B_ROWS * NE];
__device__ __half g_xh[(size_t)B_ROWS * D_IN];
__device__ __half g_w1h[(size_t)NE * D_IN * D_H];
__device__ __half g_w2h[(size_t)EH * D_OUT];
__device__ __half g_hsh[(size_t)B_ROWS * EH];
__device__ float  g_eo[(size_t)NE * B_ROWS * D_OUT];   // slot-indexed, incl. w*b2

// ---------------------------------------------------------------------------
__device__ __forceinline__ void cp16h(__half* sdst, const __half* gsrc) {
    uint32_t s = (uint32_t)__cvta_generic_to_shared(sdst);
    asm volatile("cp.async.cg.shared.global [%0], [%1], 16;\n" :: "r"(s), "l"(gsrc));
}
#define CP_COMMIT()   asm volatile("cp.async.commit_group;\n")
#define CP_WAIT_ALL() asm volatile("cp.async.wait_group 0;\n" ::: "memory")

__device__ __forceinline__ void cvt_f4(const float4* __restrict__ src,
                                       uint2* __restrict__ dst, int i) {
    float4 v = src[i];
    union { __half2 h2[2]; uint2 u; } cvt;
    cvt.h2[0] = __floats2half2_rn(v.x, v.y);
    cvt.h2[1] = __floats2half2_rn(v.z, v.w);
    dst[i] = cvt.u;
}

// ---------------------------------------------------------------------------
// Fused prep: gate (blocks [0,GB_GATE)) + x/w1 fp32->fp16 conversions.
// ---------------------------------------------------------------------------
__global__ void prep_kernel(const float* __restrict__ x, const float* __restrict__ gw,
                            const float* __restrict__ gb,
                            const float4* __restrict__ w1f4) {
    const int b = blockIdx.x;
    const int tid = threadIdx.x;

    if (b >= GB_GATE) {
        if (b < PB_W10) cvt_f4((const float4*)x, (uint2*)g_xh, (b - PB_X0) * 256 + tid);
        else            cvt_f4(w1f4, (uint2*)g_w1h, (b - PB_W10) * 256 + tid);
        return;
    }

    // Gate section: one warp per row (proven)
    int warp = (b * 256 + tid) >> 5;
    int lane = tid & 31;
    const float* xr = x + (size_t)warp * D_IN;
    float acc[NE];
#pragma unroll
    for (int e = 0; e < NE; e++) acc[e] = 0.f;
    for (int i = lane; i < D_IN; i += 32) {
        float xv = xr[i];
        const float* g = gw + i * NE;
#pragma unroll
        for (int e = 0; e < NE; e++) acc[e] += xv * g[e];
    }
#pragma unroll
    for (int e = 0; e < NE; e++)
#pragma unroll
        for (int off = 16; off > 0; off >>= 1)
            acc[e] += __shfl_xor_sync(0xffffffffu, acc[e], off);
    if (lane == 0) {
        const float invT = 0.36787944117144233f;
        float p[NE]; float mx = -1e30f;
#pragma unroll
        for (int e = 0; e < NE; e++) { p[e] = (acc[e] + gb[e]) * invT; mx = fmaxf(mx, p[e]); }
        float sum = 0.f;
#pragma unroll
        for (int e = 0; e < NE; e++) { p[e] = expf(p[e] - mx); sum += p[e]; }
        float inv = 1.f / sum;
#pragma unroll
        for (int e = 0; e < NE; e++) p[e] *= inv;
        bool sel[NE];
#pragma unroll
        for (int e = 0; e < NE; e++) sel[e] = false;
        for (int t = 0; t < NACT; t++) {
            int bi = -1; float bv = -1.f;
#pragma unroll
            for (int e = 0; e < NE; e++)
                if (!sel[e] && p[e] > bv) { bv = p[e]; bi = e; }
            sel[bi] = true;
        }
        float ws = 0.f;
#pragma unroll
        for (int e = 0; e < NE; e++) if (sel[e]) ws += p[e];
        float wi = 1.f / (ws + 1e-8f);
#pragma unroll
        for (int e = 0; e < NE; e++) {
            float wv = sel[e] ? p[e] * wi : 0.f;
            g_w[warp * NE + e] = wv;
            if (sel[e]) {
                int pos = atomicAdd(&g_cnt[e], 1);
                g_rows[e][pos] = warp;
                g_slot[warp * NE + e] = pos;
            }
        }
    }
}

// ---------------------------------------------------------------------------
// Row-gathered fp16 GEMM: CTA 128x128, 4 warps (2x2), warp tile 64x64,
// BK=64, 2-stage, 2 CTAs/SM. Halves smem fragment-read replication.
// MODE 0: FFN1 -> g_hsh (scatter); extra z-slice (z==NE) converts w2.
// MODE 1: FFN2 -> g_eo[e] (slot-contiguous), epilogue adds w*b2.
// ---------------------------------------------------------------------------
template <int MODE>
__global__ void __launch_bounds__(128, 2) gemm_h(const float* __restrict__ bias,
                                                 const float4* __restrict__ w2f4) {
    extern __shared__ __align__(16) __half sm[];
    __shared__ int sidx[128];

    const int tid  = threadIdx.x;
    const int z    = blockIdx.z;                        // expert (or NE = w2 convert)
    const int row0 = blockIdx.y * 128;
    const int col0 = blockIdx.x * 128;

    if (MODE == 0 && z == NE) {
        // w2 fp32->fp16 conversion hidden under GEMM1: 1024 blocks x 128 thr x 64 f4
        int bid = blockIdx.y * gridDim.x + blockIdx.x;  // 0..1023
        int base = bid * 128 + tid;
#pragma unroll
        for (int k = 0; k < 64; k++)
            cvt_f4(w2f4, (uint2*)g_w2h, base + k * 131072);
        return;
    }

    const int cnt = g_cnt[z];
    if (row0 >= cnt) return;
    {
        int gr = row0 + tid;
        sidx[tid] = g_rows[z][gr < cnt ? gr : cnt - 1];
    }
    __syncthreads();

    const int    KT  = (MODE == 0) ? (D_IN / BK) : (D_H / BK);     // 16 / 64
    const size_t ldB = (MODE == 0) ? D_H : D_OUT;
    const __half* Ag = (MODE == 0) ? g_xh
                                   : g_hsh + (size_t)z * D_H;
    const __half* Bg = (MODE == 0) ? g_w1h + (size_t)z * D_IN * D_H + col0
                                   : g_w2h + (size_t)z * D_H * D_OUT + col0;

    wmma::fragment<wmma::accumulator, 16, 16, 16, float> c[4][4];
#pragma unroll
    for (int i = 0; i < 4; i++)
#pragma unroll
        for (int j = 0; j < 4; j++) wmma::fill_fragment(c[i][j], 0.f);

    auto load_stage = [&](int st, int k0) {
        __half* As = sm + st * STG_H;
        __half* Bs = As + ASTG_H;
#pragma unroll
        for (int f = tid; f < 1024; f += 128) {         // A: 128 rows x 8 segs
            int r = f >> 3, sg = f & 7;
            size_t arow = (MODE == 0) ? (size_t)sidx[r] * D_IN : (size_t)sidx[r] * EH;
            cp16h(&As[r * LDA + sg * 8], Ag + arow + k0 + sg * 8);
        }
#pragma unroll
        for (int f = tid; f < 1024; f += 128) {         // B: 64 rows x 16 segs
            int r = f >> 4, sg = f & 15;
            cp16h(&Bs[r * LDB + sg * 8], Bg + (size_t)(k0 + r) * ldB + sg * 8);
        }
        CP_COMMIT();
    };

    const int wid = tid >> 5, lane = tid & 31;
    const int wm = wid >> 1;      // 0..1 (64-row block)
    const int wn = wid & 1;       // 0..1 (64-col block)

    load_stage(0, 0);
    for (int kt = 0; kt < KT; kt++) {
        CP_WAIT_ALL();
        __syncthreads();
        if (kt + 1 < KT) load_stage((kt + 1) & 1, (kt + 1) * BK);
        const __half* As = sm + (kt & 1) * STG_H;
        const __half* Bs = As + ASTG_H;
#pragma unroll
        for (int kk = 0; kk < BK; kk += 16) {
            wmma::fragment<wmma::matrix_a, 16, 16, 16, __half, wmma::row_major> a[4];
            wmma::fragment<wmma::matrix_b, 16, 16, 16, __half, wmma::row_major> b[4];
#pragma unroll
            for (int i = 0; i < 4; i++)
                wmma::load_matrix_sync(a[i], &As[(wm * 64 + i * 16) * LDA + kk], LDA);
#pragma unroll
            for (int j = 0; j < 4; j++)
                wmma::load_matrix_sync(b[j], &Bs[kk * LDB + wn * 64 + j * 16], LDB);
#pragma unroll
            for (int i = 0; i < 4; i++)
#pragma unroll
                for (int j = 0; j < 4; j++)
                    wmma::mma_sync(c[i][j], a[i], b[j], c[i][j]);
        }
    }
    __syncthreads();

    // Epilogue: per-warp 16x68 fp32 scratch on dead pipeline smem.
    // Each lane covers 2 adjacent columns of the 64-wide warp tile.
    float* scw = reinterpret_cast<float*>(sm) + wid * (16 * 68);
    const int gc0 = col0 + wn * 64 + lane * 2;
    const int bstride = (MODE == 0) ? D_H : D_OUT;
    const float bv0 = bias[(size_t)z * bstride + gc0];
    const float bv1 = bias[(size_t)z * bstride + gc0 + 1];

#pragma unroll
    for (int i = 0; i < 4; i++) {
#pragma unroll
        for (int j = 0; j < 4; j++)
            wmma::store_matrix_sync(scw + j * 16, c[i][j], 68, wmma::mem_row_major);
        __syncwarp();
        int slot0 = wm * 64 + i * 16;
#pragma unroll
        for (int r = 0; r < 16; r++) {
            int slot = slot0 + r;
            int gslot = row0 + slot;
            int row = sidx[slot];
            float wv = g_w[row * NE + z];
            float v0 = scw[r * 68 + lane * 2];
            float v1 = scw[r * 68 + lane * 2 + 1];
            if (MODE == 0) {
                if (gslot < cnt) {
                    float h0 = fmaxf(v0 + bv0, 0.f) * wv;
                    float h1 = fmaxf(v1 + bv1, 0.f) * wv;
                    *reinterpret_cast<__half2*>(&g_hsh[(size_t)row * EH + (size_t)z * D_H + gc0]) =
                        __floats2half2_rn(h0, h1);
                }
            } else {
                float2 o;
                o.x = v0 + wv * bv0;
                o.y = v1 + wv * bv1;
                *reinterpret_cast<float2*>(&g_eo[((size_t)z * B_ROWS + gslot) * D_OUT + gc0]) = o;
            }
        }
        __syncwarp();
    }
}

// ---------------------------------------------------------------------------
// finish (proven): per row sum per-camp expert slots, PH epilogue.
// ---------------------------------------------------------------------------
__global__ void finish_kernel(const float* __restrict__ alpha,
                              const float* __restrict__ beta, float* __restrict__ out) {
    __shared__ float sw[NE];
    __shared__ int   ssl[NE];
    __shared__ float red1[8], red2[8];
    __shared__ float sph;
    const int b = blockIdx.x, tid = threadIdx.x;
    if (tid < NE) {
        sw[tid]  = g_w[b * NE + tid];
        ssl[tid] = g_slot[b * NE + tid];
    }
    __syncthreads();
    const size_t SEC = (size_t)B_ROWS * D_OUT;
    float d[4]; float s1 = 0.f, s2 = 0.f;
#pragma unroll
    for (int t = 0; t < 4; t++) {
        int o = tid + 256 * t;
        float a = 0.f, g = 0.f;
#pragma unroll
        for (int e = 0; e < 4; e++) {
            if (sw[e] != 0.f)
                a += g_eo[((size_t)e * B_ROWS + ssl[e]) * D_OUT + o];
            if (sw[4 + e] != 0.f)
                g += g_eo[((size_t)(4 + e) * B_ROWS + ssl[4 + e]) * D_OUT + o];
        }
        out[SEC + (size_t)b * D_OUT + o] = a;
        out[2 * SEC + (size_t)b * D_OUT + o] = g;
        float dd = a - g; d[t] = dd; s1 += dd; s2 += dd * dd;
    }
#pragma unroll
    for (int off = 16; off > 0; off >>= 1) {
        s1 += __shfl_xor_sync(0xffffffffu, s1, off);
        s2 += __shfl_xor_sync(0xffffffffu, s2, off);
    }
    if ((tid & 31) == 0) { red1[tid >> 5] = s1; red2[tid >> 5] = s2; }
    __syncthreads();
    if (tid == 0) {
        float t1 = 0.f, t2 = 0.f;
#pragma unroll
        for (int w = 0; w < 8; w++) { t1 += red1[w]; t2 += red2[w]; }
        float l2 = sqrtf(t2);
        float mean = t1 * (1.f / D_OUT);
        float var = t2 * (1.f / D_OUT) - mean * mean;
        float zz = alpha[0] * (l2 * (1.f + var)) + beta[0];
        sph = 2.f / (1.f + expf(-zz));
    }
    __syncthreads();
    float ph = sph;
#pragma unroll
    for (int t = 0; t < 4; t++) {
        int o = tid + 256 * t;
        out[(size_t)b * D_OUT + o] = d[t] * ph;
    }
}

// ---------------------------------------------------------------------------
extern "C" void kernel_launch(void* const* d_in, const int* in_sizes, int n_in,
                              void* d_out, int out_size) {
    (void)in_sizes; (void)n_in; (void)out_size;
    const float* x  = (const float*)d_in[0];
    const float* gw = (const float*)d_in[1];
    const float* gb = (const float*)d_in[2];
    const float* w1 = (const float*)d_in[3];
    const float* b1 = (const float*)d_in[4];
    const float* w2 = (const float*)d_in[5];
    const float* b2 = (const float*)d_in[6];
    const float* pa = (const float*)d_in[7];
    const float* pb = (const float*)d_in[8];
    float* out = (float*)d_out;

    cudaFuncSetAttribute(gemm_h<0>, cudaFuncAttributeMaxDynamicSharedMemorySize, SMEM_BYTES);
    cudaFuncSetAttribute(gemm_h<1>, cudaFuncAttributeMaxDynamicSharedMemorySize, SMEM_BYTES);

    void* cnt_ptr = nullptr;
    cudaGetSymbolAddress(&cnt_ptr, g_cnt);
    cudaMemsetAsync(cnt_ptr, 0, NE * sizeof(int));

    prep_kernel<<<PB_END, 256>>>(x, gw, gb, (const float4*)w1);

    gemm_h<0><<<dim3(D_H / 128, B_ROWS / 128, NE + 1), 128, SMEM_BYTES>>>(b1, (const float4*)w2);
    gemm_h<1><<<dim3(D_OUT / 128, B_ROWS / 128, NE), 128, SMEM_BYTES>>>(b2, nullptr);
    finish_kernel<<<B_ROWS, 256>>>(pa, pb, out);
}